// round 15
// baseline (speedup 1.0000x reference)
#include <cuda_runtime.h>
#include <cuda_fp16.h>

#define cB 128
#define cN 128
#define cM 16
#define cK 8
#define cH 16
#define cD 64
#define cE 262144
#define NSUM 16384

// ---------------- device scratch (no allocations allowed) ----------------
__device__ __align__(16) float  g_feat[cB * cK * cN * cM];   // 8 MB
__device__ __align__(16) __half g_h1[NSUM * cM * cH];        // 8.4 MB
__device__ __align__(16) __half g_h2[NSUM * cM * cD];        // 33.5 MB
__device__ int g_cnt[NSUM];
__device__ int g_rowptr[NSUM + 1];
__device__ int g_cursor[NSUM];
__device__ int g_colsrc[cE];

__device__ __forceinline__ void acc8(float* a, uint4 v) {
    const __half2* p = (const __half2*)&v;
    #pragma unroll
    for (int j = 0; j < 4; j++) {
        const float2 f = __half22float2(p[j]);
        a[2 * j] += f.x; a[2 * j + 1] += f.y;
    }
}
__device__ __forceinline__ void fma8(float* a, uint4 v, float s) {
    const __half2* p = (const __half2*)&v;
    #pragma unroll
    for (int j = 0; j < 4; j++) {
        const float2 f = __half22float2(p[j]);
        a[2 * j] = fmaf(s, f.x, a[2 * j]);
        a[2 * j + 1] = fmaf(s, f.y, a[2 * j + 1]);
    }
}
// pack 8 floats into a uint4 of halves
__device__ __forceinline__ uint4 pack8(const float* a) {
    uint4 pk;
    __half2* pp = (__half2*)&pk;
    #pragma unroll
    for (int j = 0; j < 4; j++) pp[j] = __floats2half2_rn(a[2 * j], a[2 * j + 1]);
    return pk;
}

// ---------------- K1: polynomial filter ----------------
__global__ void __launch_bounds__(512) k_poly(const float* __restrict__ lap,
                                              const float* __restrict__ W0) {
    extern __shared__ float sm[];
    float* lapS = sm;                  // [128][129]
    float* buf0 = lapS + 128 * 129;    // [128][20]
    float* buf1 = buf0 + 128 * 20;
    const int b = blockIdx.x;
    const int t = threadIdx.x;

    const float* lapG = lap + (size_t)b * cN * cN;
    for (int i = t; i < cN * cN; i += 512)
        lapS[(i >> 7) * 129 + (i & 127)] = lapG[i];

    const float* w0G = W0 + (size_t)b * cN * cM;
    float* featG = g_feat + (size_t)b * (cK * cN * cM);
    for (int i = t; i < cN * cM; i += 512) {
        float v = w0G[i];
        buf0[(i >> 4) * 20 + (i & 15)] = v;
        featG[i] = v;
    }
    __syncthreads();

    const int n = t >> 2, mg = t & 3;
    float* Wc = buf0;
    float* Wn = buf1;
    const float* lrow = lapS + n * 129;
    for (int k = 1; k < cK; k++) {
        float a0 = 0.f, a1 = 0.f, a2 = 0.f, a3 = 0.f;
        #pragma unroll 8
        for (int j = 0; j < cN; j++) {
            const float l = lrow[j];
            const float4 w = *(const float4*)(Wc + j * 20 + mg * 4);
            a0 = fmaf(l, w.x, a0);
            a1 = fmaf(l, w.y, a1);
            a2 = fmaf(l, w.z, a2);
            a3 = fmaf(l, w.w, a3);
        }
        *(float4*)(Wn + n * 20 + mg * 4) = make_float4(a0, a1, a2, a3);
        ((float4*)(featG + k * (cN * cM)))[t] = make_float4(a0, a1, a2, a3);
        __syncthreads();
        float* tmp = Wc; Wc = Wn; Wn = tmp;
    }
}

// ---------------- K1b: MLP(K->H) + BatchNorm + relu -> g_h1 fp16 ----------------
__global__ void __launch_bounds__(256) k_mlpbn(const float* __restrict__ mlpW,
                                               const float* __restrict__ mlpb,
                                               const float* __restrict__ bng,
                                               const float* __restrict__ bnb) {
    __shared__ float wS[cK * cH];
    __shared__ float bS[cH];
    __shared__ float red[8][32];
    __shared__ float scaleS[cH], shiftS[cH];
    const int b = blockIdx.x, t = threadIdx.x;
    if (t < cK * cH) wS[t] = mlpW[t];
    if (t < cH) bS[t] = mlpb[t];
    __syncthreads();

    const float* fG = g_feat + (size_t)b * (cK * cN * cM);
    float sum[cH], sq[cH];
    #pragma unroll
    for (int c = 0; c < cH; c++) { sum[c] = 0.f; sq[c] = 0.f; }

    for (int r = t; r < cN * cM; r += 256) {
        float f[cK];
        #pragma unroll
        for (int k = 0; k < cK; k++) f[k] = fG[k * (cN * cM) + r];
        #pragma unroll
        for (int c = 0; c < cH; c++) {
            float h = bS[c];
            #pragma unroll
            for (int k = 0; k < cK; k++) h = fmaf(f[k], wS[k * cH + c], h);
            sum[c] += h; sq[c] += h * h;
        }
    }
    #pragma unroll
    for (int c = 0; c < cH; c++)
        for (int o = 16; o; o >>= 1) {
            sum[c] += __shfl_xor_sync(0xffffffffu, sum[c], o);
            sq[c]  += __shfl_xor_sync(0xffffffffu, sq[c],  o);
        }
    const int wid = t >> 5, lane = t & 31;
    if (lane == 0) {
        #pragma unroll
        for (int c = 0; c < cH; c++) { red[wid][c] = sum[c]; red[wid][16 + c] = sq[c]; }
    }
    __syncthreads();
    if (t < 32) {
        float v = 0.f;
        for (int w2 = 0; w2 < 8; w2++) v += red[w2][t];
        red[0][t] = v;
    }
    __syncthreads();
    if (t < cH) {
        const float mu = red[0][t] * (1.f / 2048.f);
        const float var = red[0][16 + t] * (1.f / 2048.f) - mu * mu;
        const float sc = bng[t] * rsqrtf(var + 1e-5f);
        scaleS[t] = sc;
        shiftS[t] = bnb[t] - mu * sc;
    }
    __syncthreads();

    __half* h1G = g_h1 + (size_t)b * (cN * cM * cH);
    for (int r = t; r < cN * cM; r += 256) {
        float f[cK];
        #pragma unroll
        for (int k = 0; k < cK; k++) f[k] = fG[k * (cN * cM) + r];
        float o[cH];
        #pragma unroll
        for (int c = 0; c < cH; c++) {
            float h = bS[c];
            #pragma unroll
            for (int k = 0; k < cK; k++) h = fmaf(f[k], wS[k * cH + c], h);
            o[c] = fmaxf(fmaf(h, scaleS[c], shiftS[c]), 0.f);
        }
        uint4* dst = (uint4*)(h1G + r * cH);
        dst[0] = pack8(o);
        dst[1] = pack8(o + 8);
    }
}

// ---------------- CSR build ----------------
__global__ void k_zero() {
    int i = blockIdx.x * blockDim.x + threadIdx.x;
    if (i < NSUM) g_cnt[i] = 0;
}
__global__ void k_hist(const int* __restrict__ ei) {
    const int stride = gridDim.x * blockDim.x;
    for (int e = blockIdx.x * blockDim.x + threadIdx.x; e < cE; e += stride)
        atomicAdd(&g_cnt[ei[cE + e]], 1);
}
__global__ void __launch_bounds__(512) k_scan() {
    __shared__ int wsum[16], woff[16];
    const int t = threadIdx.x, lane = t & 31, wid = t >> 5;
    const int base = t * 32;
    int s = 0;
    for (int i = 0; i < 32; i++) s += g_cnt[base + i];
    int v = s;
    for (int o = 1; o < 32; o <<= 1) {
        int u = __shfl_up_sync(0xffffffffu, v, o);
        if (lane >= o) v += u;
    }
    if (lane == 31) wsum[wid] = v;
    __syncthreads();
    if (t == 0) {
        int r = 0;
        for (int w2 = 0; w2 < 16; w2++) { woff[w2] = r; r += wsum[w2]; }
    }
    __syncthreads();
    int run = woff[wid] + (v - s);
    for (int i = 0; i < 32; i++) {
        const int c = g_cnt[base + i];
        g_rowptr[base + i] = run;
        g_cursor[base + i] = run;
        run += c;
    }
    if (t == 511) g_rowptr[NSUM] = run;
}
__global__ void k_scatter(const int* __restrict__ ei) {
    const int stride = gridDim.x * blockDim.x;
    for (int e = blockIdx.x * blockDim.x + threadIdx.x; e < cE; e += stride) {
        const int d = ei[cE + e];
        const int p = atomicAdd(&g_cursor[d], 1);
        g_colsrc[p] = ei[e];
    }
}

// ---------------- inline-PTX m16n8k16 HMMA accumulate ----------------
// Accumulates C[16 x NT*8] += A[16 x 16*KT] (row-major, lda halves) @ Bt^T into c[NT][4].
// Bt stored n-major [NT*8][ldb halves] (k contiguous per n == col-major B).
// Fragment map: c[nt][0,1] -> (row g, cols nt*8+2tg,+1); c[nt][2,3] -> (row g+8, same).
template <int KT, int NT>
__device__ __forceinline__ void mma_accum(const __half* __restrict__ A, int lda,
                                          const __half* __restrict__ Bt, int ldb,
                                          int lane, float (*c)[4]) {
    const int g = lane >> 2, tg = lane & 3;
    #pragma unroll
    for (int kt = 0; kt < KT; kt++) {
        const int k0 = kt * 16 + 2 * tg;
        const unsigned a0 = *(const unsigned*)(A + g * lda + k0);
        const unsigned a1 = *(const unsigned*)(A + (g + 8) * lda + k0);
        const unsigned a2 = *(const unsigned*)(A + g * lda + k0 + 8);
        const unsigned a3 = *(const unsigned*)(A + (g + 8) * lda + k0 + 8);
        #pragma unroll
        for (int nt = 0; nt < NT; nt++) {
            const __half* bp = Bt + (nt * 8 + g) * ldb + k0;
            const unsigned b0 = *(const unsigned*)(bp);
            const unsigned b1 = *(const unsigned*)(bp + 8);
            asm volatile(
                "mma.sync.aligned.m16n8k16.row.col.f32.f16.f16.f32 "
                "{%0,%1,%2,%3}, {%4,%5,%6,%7}, {%8,%9}, {%0,%1,%2,%3};\n"
                : "+f"(c[nt][0]), "+f"(c[nt][1]), "+f"(c[nt][2]), "+f"(c[nt][3])
                : "r"(a0), "r"(a1), "r"(a2), "r"(a3), "r"(b0), "r"(b1));
        }
    }
}

// ---------------- K3: fused GIN layer 1 (1 warp/node, warp-synchronous) ----------------
__global__ void __launch_bounds__(256) k_gin1(const float* __restrict__ eps1p,
                                              const float* __restrict__ W1a,
                                              const float* __restrict__ b1a,
                                              const float* __restrict__ W1b,
                                              const float* __restrict__ b1b) {
    extern __shared__ char smraw[];
    float*  ba  = (float*)smraw;               // 64
    float*  bb  = ba + 64;                     // 64
    __half* zt  = (__half*)(bb + 64);          // [128][24]
    __half* at  = zt + 128 * 24;               // [128][72]
    __half* wta = at + 128 * 72;               // [64][24]  n-major, k inner
    __half* wtb = wta + 64 * 24;               // [64][72]
    const int t = threadIdx.x, blk = blockIdx.x;

    for (int i = t; i < 1024; i += 256) {
        const int k = i >> 6, n = i & 63;
        wta[n * 24 + k] = __float2half(W1a[i]);
    }
    for (int i = t; i < 4096; i += 256) {
        const int k = i >> 6, n = i & 63;
        wtb[n * 72 + k] = __float2half(W1b[i]);
    }
    if (t < 64) { ba[t] = b1a[t]; bb[t] = b1b[t]; }
    const float eps1 = 1.f + eps1p[0];
    __syncthreads();   // the ONLY block sync: weights/biases visible to all warps

    const int w = t >> 5, lane = t & 31;
    const int node = blk * 8 + w;
    {
        float a[8];
        #pragma unroll
        for (int j = 0; j < 8; j++) a[j] = 0.f;
        const int s0 = g_rowptr[node], s1 = g_rowptr[node + 1];
        int e = s0;
        // 8-edge unroll: 8 LDG.128 in flight per warp
        for (; e + 8 <= s1; e += 8) {
            const uint4* p[8];
            #pragma unroll
            for (int i = 0; i < 8; i++)
                p[i] = (const uint4*)(g_h1 + g_colsrc[e + i] * (cM * cH));
            uint4 v[8];
            #pragma unroll
            for (int i = 0; i < 8; i++) v[i] = p[i][lane];
            #pragma unroll
            for (int i = 0; i < 8; i++) acc8(a, v[i]);
        }
        for (; e + 4 <= s1; e += 4) {
            const uint4* p[4];
            #pragma unroll
            for (int i = 0; i < 4; i++)
                p[i] = (const uint4*)(g_h1 + g_colsrc[e + i] * (cM * cH));
            uint4 v[4];
            #pragma unroll
            for (int i = 0; i < 4; i++) v[i] = p[i][lane];
            #pragma unroll
            for (int i = 0; i < 4; i++) acc8(a, v[i]);
        }
        for (; e < s1; e++) {
            const uint4 v = ((const uint4*)(g_h1 + g_colsrc[e] * (cM * cH)))[lane];
            acc8(a, v);
        }
        const uint4 vs = ((const uint4*)(g_h1 + node * (cM * cH)))[lane];
        fma8(a, vs, eps1);
        // lane covers elements 8*lane..8*lane+7: m = lane>>1, c0 = (lane&1)*8
        *(uint4*)(zt + (w * 16 + (lane >> 1)) * 24 + (lane & 1) * 8) = pack8(a);
    }
    __syncwarp();

    const int g = lane >> 2, tg = lane & 3;
    // GEMM1: z @ W1a  (K=16)
    float c1[8][4];
    #pragma unroll
    for (int nt = 0; nt < 8; nt++)
        #pragma unroll
        for (int j = 0; j < 4; j++) c1[nt][j] = 0.f;
    mma_accum<1, 8>(zt + w * 16 * 24, 24, wta, 24, lane, c1);
    // bias+relu+pack in registers -> at (own warp's rows only)
    #pragma unroll
    for (int nt = 0; nt < 8; nt++) {
        const int col = nt * 8 + 2 * tg;
        const float2 b = *(const float2*)(ba + col);
        *(__half2*)(at + (w * 16 + g) * 72 + col) =
            __floats2half2_rn(fmaxf(c1[nt][0] + b.x, 0.f), fmaxf(c1[nt][1] + b.y, 0.f));
        *(__half2*)(at + (w * 16 + g + 8) * 72 + col) =
            __floats2half2_rn(fmaxf(c1[nt][2] + b.x, 0.f), fmaxf(c1[nt][3] + b.y, 0.f));
    }
    __syncwarp();

    // GEMM2: a @ W1b  (K=64)
    float c2[8][4];
    #pragma unroll
    for (int nt = 0; nt < 8; nt++)
        #pragma unroll
        for (int j = 0; j < 4; j++) c2[nt][j] = 0.f;
    mma_accum<4, 8>(at + w * 16 * 72, 72, wtb, 72, lane, c2);
    // bias+relu+pack -> g_h2 directly from registers
    __half* outG = g_h2 + (size_t)(blk * 128 + w * 16) * cD;
    #pragma unroll
    for (int nt = 0; nt < 8; nt++) {
        const int col = nt * 8 + 2 * tg;
        const float2 b = *(const float2*)(bb + col);
        *(__half2*)(outG + g * cD + col) =
            __floats2half2_rn(fmaxf(c2[nt][0] + b.x, 0.f), fmaxf(c2[nt][1] + b.y, 0.f));
        *(__half2*)(outG + (g + 8) * cD + col) =
            __floats2half2_rn(fmaxf(c2[nt][2] + b.x, 0.f), fmaxf(c2[nt][3] + b.y, 0.f));
    }
}

// ---------------- K4: fused GIN layer 2 — 2 warps per node, pair-synchronous ----------------
// Warp pair (2p, 2p+1) owns one node; warp part q handles d-columns [32q, 32q+32).
// smem z buffer is reused for the GEMM1 activation (WAR fenced by pair barrier).
__global__ void __launch_bounds__(512) k_gin2(const float* __restrict__ eps2p,
                                              const float* __restrict__ W2a,
                                              const float* __restrict__ b2a,
                                              const float* __restrict__ W2b,
                                              const float* __restrict__ b2b,
                                              float* __restrict__ out) {
    extern __shared__ char smraw[];
    float*  ba  = (float*)smraw;               // 64
    float*  bb  = ba + 64;                     // 64
    __half* zt  = (__half*)(bb + 64);          // [128][72]  (z, then reused for a)
    __half* wta = zt + 128 * 72;               // [64][72]
    __half* wtb = wta + 64 * 72;               // [64][72]
    const int t = threadIdx.x, blk = blockIdx.x;

    for (int i = t; i < 4096; i += 512) {
        const int k = i >> 6, n = i & 63;
        wta[n * 72 + k] = __float2half(W2a[i]);
        wtb[n * 72 + k] = __float2half(W2b[i]);
    }
    if (t < 64) { ba[t] = b2a[t]; bb[t] = b2b[t]; }
    const float eps2 = 1.f + eps2p[0];
    __syncthreads();   // the ONLY block sync

    const int w = t >> 5, lane = t & 31;
    const int pair = w >> 1, q = w & 1;        // pair 0..7, part 0..1
    const int node = blk * 8 + pair;
    const int barid = 1 + pair;                // named barriers 1..8, 64 threads each

    // gather: this warp covers 512 halves = d-range [32q, 32q+32) over all 16 m.
    // lane covers 16 halves: m = lane>>1, d0 = q*32 + (lane&1)*16; uint4 u = m*8 + q*4 + (lane&1)*2.
    const int u = (lane >> 1) * 8 + q * 4 + (lane & 1) * 2;
    {
        float a[16];
        #pragma unroll
        for (int j = 0; j < 16; j++) a[j] = 0.f;
        const int s0 = g_rowptr[node], s1 = g_rowptr[node + 1];
        int e = s0;
        // 8-edge unroll: 16 LDG.128 in flight per warp
        for (; e + 8 <= s1; e += 8) {
            const uint4* p[8];
            #pragma unroll
            for (int i = 0; i < 8; i++)
                p[i] = (const uint4*)(g_h2 + (size_t)g_colsrc[e + i] * (cM * cD));
            uint4 v[16];
            #pragma unroll
            for (int i = 0; i < 8; i++) { v[2 * i] = p[i][u]; v[2 * i + 1] = p[i][u + 1]; }
            #pragma unroll
            for (int i = 0; i < 8; i++) { acc8(a, v[2 * i]); acc8(a + 8, v[2 * i + 1]); }
        }
        for (; e + 4 <= s1; e += 4) {
            const uint4* p[4];
            #pragma unroll
            for (int i = 0; i < 4; i++)
                p[i] = (const uint4*)(g_h2 + (size_t)g_colsrc[e + i] * (cM * cD));
            uint4 v[8];
            #pragma unroll
            for (int i = 0; i < 4; i++) { v[2 * i] = p[i][u]; v[2 * i + 1] = p[i][u + 1]; }
            #pragma unroll
            for (int i = 0; i < 4; i++) { acc8(a, v[2 * i]); acc8(a + 8, v[2 * i + 1]); }
        }
        for (; e < s1; e++) {
            const uint4* p0 = (const uint4*)(g_h2 + (size_t)g_colsrc[e] * (cM * cD));
            acc8(a, p0[u]); acc8(a + 8, p0[u + 1]);
        }
        const uint4* ps = (const uint4*)(g_h2 + (size_t)node * (cM * cD));
        fma8(a, ps[u], eps2); fma8(a + 8, ps[u + 1], eps2);
        __half* zp = zt + (pair * 16 + (lane >> 1)) * 72 + q * 32 + (lane & 1) * 16;
        *(uint4*)zp = pack8(a);
        *(uint4*)(zp + 8) = pack8(a + 8);
    }
    asm volatile("bar.sync %0, %1;" :: "r"(barid), "r"(64) : "memory");   // z tile ready

    const int g = lane >> 2, tg = lane & 3;
    const __half* Atile = zt + pair * 16 * 72;

    // GEMM1: z @ W2a  (K=64), this warp computes cols [32q, 32q+32)
    float c1[4][4];
    #pragma unroll
    for (int nt = 0; nt < 4; nt++)
        #pragma unroll
        for (int j = 0; j < 4; j++) c1[nt][j] = 0.f;
    mma_accum<4, 4>(Atile, 72, wta + q * 32 * 72, 72, lane, c1);
    asm volatile("bar.sync %0, %1;" :: "r"(barid), "r"(64) : "memory");   // both warps done reading z

    // bias+relu+pack -> reuse z buffer as activation
    #pragma unroll
    for (int nt = 0; nt < 4; nt++) {
        const int col = q * 32 + nt * 8 + 2 * tg;
        const float2 b = *(const float2*)(ba + col);
        *(__half2*)(zt + (pair * 16 + g) * 72 + col) =
            __floats2half2_rn(fmaxf(c1[nt][0] + b.x, 0.f), fmaxf(c1[nt][1] + b.y, 0.f));
        *(__half2*)(zt + (pair * 16 + g + 8) * 72 + col) =
            __floats2half2_rn(fmaxf(c1[nt][2] + b.x, 0.f), fmaxf(c1[nt][3] + b.y, 0.f));
    }
    asm volatile("bar.sync %0, %1;" :: "r"(barid), "r"(64) : "memory");   // activation ready

    // GEMM2: a @ W2b  (K=64), cols [32q, 32q+32)
    float c2[4][4];
    #pragma unroll
    for (int nt = 0; nt < 4; nt++)
        #pragma unroll
        for (int j = 0; j < 4; j++) c2[nt][j] = 0.f;
    mma_accum<4, 4>(Atile, 72, wtb + q * 32 * 72, 72, lane, c2);

    // bias + relu + m-sum in registers/shuffles (rows g, g+8 local; 8 g-values via shfl)
    #pragma unroll
    for (int nt = 0; nt < 4; nt++) {
        const int col = q * 32 + nt * 8 + 2 * tg;
        const float2 b = *(const float2*)(bb + col);
        float s0 = fmaxf(c2[nt][0] + b.x, 0.f) + fmaxf(c2[nt][2] + b.x, 0.f);
        float s1 = fmaxf(c2[nt][1] + b.y, 0.f) + fmaxf(c2[nt][3] + b.y, 0.f);
        #pragma unroll
        for (int o = 4; o <= 16; o <<= 1) {
            s0 += __shfl_xor_sync(0xffffffffu, s0, o);
            s1 += __shfl_xor_sync(0xffffffffu, s1, o);
        }
        if (g == 0)
            *(float2*)(out + (size_t)node * 64 + col) = make_float2(s0, s1);
    }
}

// ---------------- launch ----------------
extern "C" void kernel_launch(void* const* d_in, const int* in_sizes, int n_in,
                              void* d_out, int out_size) {
    (void)in_sizes; (void)n_in; (void)out_size;
    const float* lap  = (const float*)d_in[0];
    const float* W0   = (const float*)d_in[1];
    const float* mlpW = (const float*)d_in[2];
    const float* mlpb = (const float*)d_in[3];
    const float* bng  = (const float*)d_in[4];
    const float* bnb  = (const float*)d_in[5];
    const float* eps1 = (const float*)d_in[6];
    const float* W1a  = (const float*)d_in[7];
    const float* b1a  = (const float*)d_in[8];
    const float* W1b  = (const float*)d_in[9];
    const float* b1b  = (const float*)d_in[10];
    const float* eps2 = (const float*)d_in[11];
    const float* W2a  = (const float*)d_in[12];
    const float* b2a  = (const float*)d_in[13];
    const float* W2b  = (const float*)d_in[14];
    const float* b2b  = (const float*)d_in[15];
    const int*   ei   = (const int*)d_in[16];
    float* out = (float*)d_out;

    const int sm1 = (128 * 129 + 2 * 128 * 20) * (int)sizeof(float);
    const int sm3 = 128 * 4 + (128 * 24 + 128 * 72 + 64 * 24 + 64 * 72) * 2;   // 37,376 B
    const int sm4 = 128 * 4 + (128 * 72 + 2 * 64 * 72) * 2;                    // 37,376 B
    cudaFuncSetAttribute(k_poly, cudaFuncAttributeMaxDynamicSharedMemorySize, sm1);
    cudaFuncSetAttribute(k_gin1, cudaFuncAttributeMaxDynamicSharedMemorySize, sm3);
    cudaFuncSetAttribute(k_gin2, cudaFuncAttributeMaxDynamicSharedMemorySize, sm4);

    k_poly<<<cB, 512, sm1>>>(lap, W0);
    k_zero<<<(NSUM + 255) / 256, 256>>>();
    k_hist<<<256, 256>>>(ei);
    k_mlpbn<<<cB, 256>>>(mlpW, mlpb, bng, bnb);
    k_scan<<<1, 512>>>();
    k_scatter<<<256, 256>>>(ei);
    k_gin1<<<NSUM / 8, 256, sm3>>>(eps1, W1a, b1a, W1b, b1b);
    k_gin2<<<NSUM / 8, 512, sm4>>>(eps2, W2a, b2a, W2b, b2b, out);
}

// round 16
// speedup vs baseline: 1.1628x; 1.1628x over previous
#include <cuda_runtime.h>
#include <cuda_fp16.h>

#define cB 128
#define cN 128
#define cM 16
#define cK 8
#define cH 16
#define cD 64
#define cE 262144
#define NSUM 16384

// ---------------- device scratch (no allocations allowed) ----------------
__device__ __align__(16) float  g_feat[cB * cK * cN * cM];   // 8 MB
__device__ __align__(16) __half g_h1[NSUM * cM * cH];        // 8.4 MB
__device__ __align__(16) __half g_h2[NSUM * cM * cD];        // 33.5 MB
__device__ int g_cnt[NSUM];
__device__ int g_rowptr[NSUM + 1];
__device__ int g_cursor[NSUM];
__device__ int g_colsrc[cE];

__device__ __forceinline__ void acc8(float* a, uint4 v) {
    const __half2* p = (const __half2*)&v;
    #pragma unroll
    for (int j = 0; j < 4; j++) {
        const float2 f = __half22float2(p[j]);
        a[2 * j] += f.x; a[2 * j + 1] += f.y;
    }
}
__device__ __forceinline__ void fma8(float* a, uint4 v, float s) {
    const __half2* p = (const __half2*)&v;
    #pragma unroll
    for (int j = 0; j < 4; j++) {
        const float2 f = __half22float2(p[j]);
        a[2 * j] = fmaf(s, f.x, a[2 * j]);
        a[2 * j + 1] = fmaf(s, f.y, a[2 * j + 1]);
    }
}
// pack 8 floats into a uint4 of halves
__device__ __forceinline__ uint4 pack8(const float* a) {
    uint4 pk;
    __half2* pp = (__half2*)&pk;
    #pragma unroll
    for (int j = 0; j < 4; j++) pp[j] = __floats2half2_rn(a[2 * j], a[2 * j + 1]);
    return pk;
}

// ---------------- K1: polynomial filter ----------------
__global__ void __launch_bounds__(512) k_poly(const float* __restrict__ lap,
                                              const float* __restrict__ W0) {
    extern __shared__ float sm[];
    float* lapS = sm;                  // [128][129]
    float* buf0 = lapS + 128 * 129;    // [128][20]
    float* buf1 = buf0 + 128 * 20;
    const int b = blockIdx.x;
    const int t = threadIdx.x;

    const float* lapG = lap + (size_t)b * cN * cN;
    for (int i = t; i < cN * cN; i += 512)
        lapS[(i >> 7) * 129 + (i & 127)] = lapG[i];

    const float* w0G = W0 + (size_t)b * cN * cM;
    float* featG = g_feat + (size_t)b * (cK * cN * cM);
    for (int i = t; i < cN * cM; i += 512) {
        float v = w0G[i];
        buf0[(i >> 4) * 20 + (i & 15)] = v;
        featG[i] = v;
    }
    __syncthreads();

    const int n = t >> 2, mg = t & 3;
    float* Wc = buf0;
    float* Wn = buf1;
    const float* lrow = lapS + n * 129;
    for (int k = 1; k < cK; k++) {
        float a0 = 0.f, a1 = 0.f, a2 = 0.f, a3 = 0.f;
        #pragma unroll 8
        for (int j = 0; j < cN; j++) {
            const float l = lrow[j];
            const float4 w = *(const float4*)(Wc + j * 20 + mg * 4);
            a0 = fmaf(l, w.x, a0);
            a1 = fmaf(l, w.y, a1);
            a2 = fmaf(l, w.z, a2);
            a3 = fmaf(l, w.w, a3);
        }
        *(float4*)(Wn + n * 20 + mg * 4) = make_float4(a0, a1, a2, a3);
        ((float4*)(featG + k * (cN * cM)))[t] = make_float4(a0, a1, a2, a3);
        __syncthreads();
        float* tmp = Wc; Wc = Wn; Wn = tmp;
    }
}

// ---------------- K1b: MLP(K->H) + BatchNorm + relu -> g_h1 fp16 ----------------
// h cached in smem [2048][17] fp32 (pad 17 -> conflict-free LDS.128 in pass 2).
__global__ void __launch_bounds__(256) k_mlpbn(const float* __restrict__ mlpW,
                                               const float* __restrict__ mlpb,
                                               const float* __restrict__ bng,
                                               const float* __restrict__ bnb) {
    extern __shared__ float hS[];              // [2048][17] = 139,264 B
    __shared__ float wS[cK * cH];
    __shared__ float bS[cH];
    __shared__ float red[8][32];
    __shared__ float scaleS[cH], shiftS[cH];
    const int b = blockIdx.x, t = threadIdx.x;
    if (t < cK * cH) wS[t] = mlpW[t];
    if (t < cH) bS[t] = mlpb[t];
    __syncthreads();

    const float* fG = g_feat + (size_t)b * (cK * cN * cM);
    float sum[cH], sq[cH];
    #pragma unroll
    for (int c = 0; c < cH; c++) { sum[c] = 0.f; sq[c] = 0.f; }

    for (int r = t; r < cN * cM; r += 256) {
        float f[cK];
        #pragma unroll
        for (int k = 0; k < cK; k++) f[k] = fG[k * (cN * cM) + r];
        float* hrow = hS + r * 17;
        #pragma unroll
        for (int c = 0; c < cH; c++) {
            float h = bS[c];
            #pragma unroll
            for (int k = 0; k < cK; k++) h = fmaf(f[k], wS[k * cH + c], h);
            hrow[c] = h;
            sum[c] += h; sq[c] += h * h;
        }
    }
    #pragma unroll
    for (int c = 0; c < cH; c++)
        for (int o = 16; o; o >>= 1) {
            sum[c] += __shfl_xor_sync(0xffffffffu, sum[c], o);
            sq[c]  += __shfl_xor_sync(0xffffffffu, sq[c],  o);
        }
    const int wid = t >> 5, lane = t & 31;
    if (lane == 0) {
        #pragma unroll
        for (int c = 0; c < cH; c++) { red[wid][c] = sum[c]; red[wid][16 + c] = sq[c]; }
    }
    __syncthreads();
    if (t < 32) {
        float v = 0.f;
        for (int w2 = 0; w2 < 8; w2++) v += red[w2][t];
        red[0][t] = v;
    }
    __syncthreads();
    if (t < cH) {
        const float mu = red[0][t] * (1.f / 2048.f);
        const float var = red[0][16 + t] * (1.f / 2048.f) - mu * mu;
        const float sc = bng[t] * rsqrtf(var + 1e-5f);
        scaleS[t] = sc;
        shiftS[t] = bnb[t] - mu * sc;
    }
    __syncthreads();

    __half* h1G = g_h1 + (size_t)b * (cN * cM * cH);
    for (int r = t; r < cN * cM; r += 256) {
        const float* hrow = hS + r * 17;
        float o[cH];
        #pragma unroll
        for (int c = 0; c < cH; c++)
            o[c] = fmaxf(fmaf(hrow[c], scaleS[c], shiftS[c]), 0.f);
        uint4* dst = (uint4*)(h1G + r * cH);
        dst[0] = pack8(o);
        dst[1] = pack8(o + 8);
    }
}

// ---------------- CSR build ----------------
__global__ void k_zero() {
    int i = blockIdx.x * blockDim.x + threadIdx.x;
    if (i < NSUM) g_cnt[i] = 0;
}
__global__ void k_hist(const int* __restrict__ ei) {
    const int stride = gridDim.x * blockDim.x;
    for (int e = blockIdx.x * blockDim.x + threadIdx.x; e < cE; e += stride)
        atomicAdd(&g_cnt[ei[cE + e]], 1);
}
__global__ void __launch_bounds__(512) k_scan() {
    __shared__ int wsum[16], woff[16];
    const int t = threadIdx.x, lane = t & 31, wid = t >> 5;
    const int base = t * 32;
    int s = 0;
    for (int i = 0; i < 32; i++) s += g_cnt[base + i];
    int v = s;
    for (int o = 1; o < 32; o <<= 1) {
        int u = __shfl_up_sync(0xffffffffu, v, o);
        if (lane >= o) v += u;
    }
    if (lane == 31) wsum[wid] = v;
    __syncthreads();
    if (t == 0) {
        int r = 0;
        for (int w2 = 0; w2 < 16; w2++) { woff[w2] = r; r += wsum[w2]; }
    }
    __syncthreads();
    int run = woff[wid] + (v - s);
    for (int i = 0; i < 32; i++) {
        const int c = g_cnt[base + i];
        g_rowptr[base + i] = run;
        g_cursor[base + i] = run;
        run += c;
    }
    if (t == 511) g_rowptr[NSUM] = run;
}
__global__ void k_scatter(const int* __restrict__ ei) {
    const int stride = gridDim.x * blockDim.x;
    for (int e = blockIdx.x * blockDim.x + threadIdx.x; e < cE; e += stride) {
        const int d = ei[cE + e];
        const int p = atomicAdd(&g_cursor[d], 1);
        g_colsrc[p] = ei[e];
    }
}

// ---------------- inline-PTX m16n8k16 HMMA accumulate ----------------
// Accumulates C[16 x NT*8] += A[16 x 16*KT] (row-major, lda halves) @ Bt^T into c[NT][4].
// Bt stored n-major [NT*8][ldb halves] (k contiguous per n == col-major B).
// Fragment map: c[nt][0,1] -> (row g, cols nt*8+2tg,+1); c[nt][2,3] -> (row g+8, same).
template <int KT, int NT>
__device__ __forceinline__ void mma_accum(const __half* __restrict__ A, int lda,
                                          const __half* __restrict__ Bt, int ldb,
                                          int lane, float (*c)[4]) {
    const int g = lane >> 2, tg = lane & 3;
    #pragma unroll
    for (int kt = 0; kt < KT; kt++) {
        const int k0 = kt * 16 + 2 * tg;
        const unsigned a0 = *(const unsigned*)(A + g * lda + k0);
        const unsigned a1 = *(const unsigned*)(A + (g + 8) * lda + k0);
        const unsigned a2 = *(const unsigned*)(A + g * lda + k0 + 8);
        const unsigned a3 = *(const unsigned*)(A + (g + 8) * lda + k0 + 8);
        #pragma unroll
        for (int nt = 0; nt < NT; nt++) {
            const __half* bp = Bt + (nt * 8 + g) * ldb + k0;
            const unsigned b0 = *(const unsigned*)(bp);
            const unsigned b1 = *(const unsigned*)(bp + 8);
            asm volatile(
                "mma.sync.aligned.m16n8k16.row.col.f32.f16.f16.f32 "
                "{%0,%1,%2,%3}, {%4,%5,%6,%7}, {%8,%9}, {%0,%1,%2,%3};\n"
                : "+f"(c[nt][0]), "+f"(c[nt][1]), "+f"(c[nt][2]), "+f"(c[nt][3])
                : "r"(a0), "r"(a1), "r"(a2), "r"(a3), "r"(b0), "r"(b1));
        }
    }
}

// ---------------- K3: fused GIN layer 1 (1 warp/node, warp-synchronous) ----------------
__global__ void __launch_bounds__(256) k_gin1(const float* __restrict__ eps1p,
                                              const float* __restrict__ W1a,
                                              const float* __restrict__ b1a,
                                              const float* __restrict__ W1b,
                                              const float* __restrict__ b1b) {
    extern __shared__ char smraw[];
    float*  ba  = (float*)smraw;               // 64
    float*  bb  = ba + 64;                     // 64
    __half* zt  = (__half*)(bb + 64);          // [128][24]
    __half* at  = zt + 128 * 24;               // [128][72]
    __half* wta = at + 128 * 72;               // [64][24]  n-major, k inner
    __half* wtb = wta + 64 * 24;               // [64][72]
    const int t = threadIdx.x, blk = blockIdx.x;

    for (int i = t; i < 1024; i += 256) {
        const int k = i >> 6, n = i & 63;
        wta[n * 24 + k] = __float2half(W1a[i]);
    }
    for (int i = t; i < 4096; i += 256) {
        const int k = i >> 6, n = i & 63;
        wtb[n * 72 + k] = __float2half(W1b[i]);
    }
    if (t < 64) { ba[t] = b1a[t]; bb[t] = b1b[t]; }
    const float eps1 = 1.f + eps1p[0];
    __syncthreads();   // the ONLY block sync: weights/biases visible to all warps

    const int w = t >> 5, lane = t & 31;
    const int node = blk * 8 + w;
    {
        float a[8];
        #pragma unroll
        for (int j = 0; j < 8; j++) a[j] = 0.f;
        const int s0 = g_rowptr[node], s1 = g_rowptr[node + 1];
        int e = s0;
        for (; e + 4 <= s1; e += 4) {
            const int c0 = g_colsrc[e], c1 = g_colsrc[e + 1];
            const int c2 = g_colsrc[e + 2], c3 = g_colsrc[e + 3];
            const uint4 v0 = ((const uint4*)(g_h1 + c0 * (cM * cH)))[lane];
            const uint4 v1 = ((const uint4*)(g_h1 + c1 * (cM * cH)))[lane];
            const uint4 v2 = ((const uint4*)(g_h1 + c2 * (cM * cH)))[lane];
            const uint4 v3 = ((const uint4*)(g_h1 + c3 * (cM * cH)))[lane];
            acc8(a, v0); acc8(a, v1); acc8(a, v2); acc8(a, v3);
        }
        for (; e < s1; e++) {
            const uint4 v = ((const uint4*)(g_h1 + g_colsrc[e] * (cM * cH)))[lane];
            acc8(a, v);
        }
        const uint4 vs = ((const uint4*)(g_h1 + node * (cM * cH)))[lane];
        fma8(a, vs, eps1);
        // lane covers elements 8*lane..8*lane+7: m = lane>>1, c0 = (lane&1)*8
        *(uint4*)(zt + (w * 16 + (lane >> 1)) * 24 + (lane & 1) * 8) = pack8(a);
    }
    __syncwarp();

    const int g = lane >> 2, tg = lane & 3;
    // GEMM1: z @ W1a  (K=16)
    float c1[8][4];
    #pragma unroll
    for (int nt = 0; nt < 8; nt++)
        #pragma unroll
        for (int j = 0; j < 4; j++) c1[nt][j] = 0.f;
    mma_accum<1, 8>(zt + w * 16 * 24, 24, wta, 24, lane, c1);
    // bias+relu+pack in registers -> at (own warp's rows only)
    #pragma unroll
    for (int nt = 0; nt < 8; nt++) {
        const int col = nt * 8 + 2 * tg;
        const float2 b = *(const float2*)(ba + col);
        *(__half2*)(at + (w * 16 + g) * 72 + col) =
            __floats2half2_rn(fmaxf(c1[nt][0] + b.x, 0.f), fmaxf(c1[nt][1] + b.y, 0.f));
        *(__half2*)(at + (w * 16 + g + 8) * 72 + col) =
            __floats2half2_rn(fmaxf(c1[nt][2] + b.x, 0.f), fmaxf(c1[nt][3] + b.y, 0.f));
    }
    __syncwarp();

    // GEMM2: a @ W1b  (K=64)
    float c2[8][4];
    #pragma unroll
    for (int nt = 0; nt < 8; nt++)
        #pragma unroll
        for (int j = 0; j < 4; j++) c2[nt][j] = 0.f;
    mma_accum<4, 8>(at + w * 16 * 72, 72, wtb, 72, lane, c2);
    // bias+relu+pack -> g_h2 directly from registers
    __half* outG = g_h2 + (size_t)(blk * 128 + w * 16) * cD;
    #pragma unroll
    for (int nt = 0; nt < 8; nt++) {
        const int col = nt * 8 + 2 * tg;
        const float2 b = *(const float2*)(bb + col);
        *(__half2*)(outG + g * cD + col) =
            __floats2half2_rn(fmaxf(c2[nt][0] + b.x, 0.f), fmaxf(c2[nt][1] + b.y, 0.f));
        *(__half2*)(outG + (g + 8) * cD + col) =
            __floats2half2_rn(fmaxf(c2[nt][2] + b.x, 0.f), fmaxf(c2[nt][3] + b.y, 0.f));
    }
}

// ---------------- K4: fused GIN layer 2 — 2 warps per node, pair-synchronous ----------------
// Warp pair (2p, 2p+1) owns one node; warp part q gathers uint4 chunks [64q, 64q+64)
// with CONTIGUOUS lane addressing: each LDG.128 spans 512 contiguous bytes = 4 cache
// lines (vs 16 before) -> 4x fewer L1tex wavefronts. GEMM split: warp q computes
// output cols [32q, 32q+32). smem z buffer reused for the GEMM1 activation.
__global__ void __launch_bounds__(512) k_gin2(const float* __restrict__ eps2p,
                                              const float* __restrict__ W2a,
                                              const float* __restrict__ b2a,
                                              const float* __restrict__ W2b,
                                              const float* __restrict__ b2b,
                                              float* __restrict__ out) {
    extern __shared__ char smraw[];
    float*  ba  = (float*)smraw;               // 64
    float*  bb  = ba + 64;                     // 64
    __half* zt  = (__half*)(bb + 64);          // [128][72]  (z, then reused for a)
    __half* wta = zt + 128 * 72;               // [64][72]
    __half* wtb = wta + 64 * 72;               // [64][72]
    const int t = threadIdx.x, blk = blockIdx.x;

    for (int i = t; i < 4096; i += 512) {
        const int k = i >> 6, n = i & 63;
        wta[n * 72 + k] = __float2half(W2a[i]);
        wtb[n * 72 + k] = __float2half(W2b[i]);
    }
    if (t < 64) { ba[t] = b2a[t]; bb[t] = b2b[t]; }
    const float eps2 = 1.f + eps2p[0];
    __syncthreads();   // the ONLY block sync

    const int w = t >> 5, lane = t & 31;
    const int pair = w >> 1, q = w & 1;        // pair 0..7, part 0..1
    const int node = blk * 8 + pair;
    const int barid = 1 + pair;                // named barriers 1..8, 64 threads each

    // gather: warp q covers uint4 chunks c_lo = 64q+lane and c_hi = 64q+32+lane.
    // chunk c -> m = c>>3, halves [(c&7)*8, (c&7)*8+8) of that m-row.
    const int c_lo = 64 * q + lane;
    const int c_hi = c_lo + 32;
    {
        float alo[8], ahi[8];
        #pragma unroll
        for (int j = 0; j < 8; j++) { alo[j] = 0.f; ahi[j] = 0.f; }
        const int s0 = g_rowptr[node], s1 = g_rowptr[node + 1];
        int e = s0;
        for (; e + 4 <= s1; e += 4) {
            const uint4* p[4];
            #pragma unroll
            for (int i = 0; i < 4; i++)
                p[i] = (const uint4*)(g_h2 + (size_t)g_colsrc[e + i] * (cM * cD));
            uint4 v[8];
            #pragma unroll
            for (int i = 0; i < 4; i++) { v[2 * i] = p[i][c_lo]; v[2 * i + 1] = p[i][c_hi]; }
            #pragma unroll
            for (int i = 0; i < 4; i++) { acc8(alo, v[2 * i]); acc8(ahi, v[2 * i + 1]); }
        }
        for (; e < s1; e++) {
            const uint4* p0 = (const uint4*)(g_h2 + (size_t)g_colsrc[e] * (cM * cD));
            acc8(alo, p0[c_lo]); acc8(ahi, p0[c_hi]);
        }
        const uint4* ps = (const uint4*)(g_h2 + (size_t)node * (cM * cD));
        fma8(alo, ps[c_lo], eps2); fma8(ahi, ps[c_hi], eps2);
        *(uint4*)(zt + (pair * 16 + (c_lo >> 3)) * 72 + (c_lo & 7) * 8) = pack8(alo);
        *(uint4*)(zt + (pair * 16 + (c_hi >> 3)) * 72 + (c_hi & 7) * 8) = pack8(ahi);
    }
    asm volatile("bar.sync %0, %1;" :: "r"(barid), "r"(64) : "memory");   // z tile ready

    const int g = lane >> 2, tg = lane & 3;
    const __half* Atile = zt + pair * 16 * 72;

    // GEMM1: z @ W2a  (K=64), this warp computes cols [32q, 32q+32)
    float c1[4][4];
    #pragma unroll
    for (int nt = 0; nt < 4; nt++)
        #pragma unroll
        for (int j = 0; j < 4; j++) c1[nt][j] = 0.f;
    mma_accum<4, 4>(Atile, 72, wta + q * 32 * 72, 72, lane, c1);
    asm volatile("bar.sync %0, %1;" :: "r"(barid), "r"(64) : "memory");   // both warps done reading z

    // bias+relu+pack -> reuse z buffer as activation
    #pragma unroll
    for (int nt = 0; nt < 4; nt++) {
        const int col = q * 32 + nt * 8 + 2 * tg;
        const float2 b = *(const float2*)(ba + col);
        *(__half2*)(zt + (pair * 16 + g) * 72 + col) =
            __floats2half2_rn(fmaxf(c1[nt][0] + b.x, 0.f), fmaxf(c1[nt][1] + b.y, 0.f));
        *(__half2*)(zt + (pair * 16 + g + 8) * 72 + col) =
            __floats2half2_rn(fmaxf(c1[nt][2] + b.x, 0.f), fmaxf(c1[nt][3] + b.y, 0.f));
    }
    asm volatile("bar.sync %0, %1;" :: "r"(barid), "r"(64) : "memory");   // activation ready

    // GEMM2: a @ W2b  (K=64), cols [32q, 32q+32)
    float c2[4][4];
    #pragma unroll
    for (int nt = 0; nt < 4; nt++)
        #pragma unroll
        for (int j = 0; j < 4; j++) c2[nt][j] = 0.f;
    mma_accum<4, 4>(Atile, 72, wtb + q * 32 * 72, 72, lane, c2);

    // bias + relu + m-sum in registers/shuffles (rows g, g+8 local; 8 g-values via shfl)
    #pragma unroll
    for (int nt = 0; nt < 4; nt++) {
        const int col = q * 32 + nt * 8 + 2 * tg;
        const float2 b = *(const float2*)(bb + col);
        float s0 = fmaxf(c2[nt][0] + b.x, 0.f) + fmaxf(c2[nt][2] + b.x, 0.f);
        float s1 = fmaxf(c2[nt][1] + b.y, 0.f) + fmaxf(c2[nt][3] + b.y, 0.f);
        #pragma unroll
        for (int o = 4; o <= 16; o <<= 1) {
            s0 += __shfl_xor_sync(0xffffffffu, s0, o);
            s1 += __shfl_xor_sync(0xffffffffu, s1, o);
        }
        if (g == 0)
            *(float2*)(out + (size_t)node * 64 + col) = make_float2(s0, s1);
    }
}

// ---------------- launch ----------------
extern "C" void kernel_launch(void* const* d_in, const int* in_sizes, int n_in,
                              void* d_out, int out_size) {
    (void)in_sizes; (void)n_in; (void)out_size;
    const float* lap  = (const float*)d_in[0];
    const float* W0   = (const float*)d_in[1];
    const float* mlpW = (const float*)d_in[2];
    const float* mlpb = (const float*)d_in[3];
    const float* bng  = (const float*)d_in[4];
    const float* bnb  = (const float*)d_in[5];
    const float* eps1 = (const float*)d_in[6];
    const float* W1a  = (const float*)d_in[7];
    const float* b1a  = (const float*)d_in[8];
    const float* W1b  = (const float*)d_in[9];
    const float* b1b  = (const float*)d_in[10];
    const float* eps2 = (const float*)d_in[11];
    const float* W2a  = (const float*)d_in[12];
    const float* b2a  = (const float*)d_in[13];
    const float* W2b  = (const float*)d_in[14];
    const float* b2b  = (const float*)d_in[15];
    const int*   ei   = (const int*)d_in[16];
    float* out = (float*)d_out;

    const int sm1 = (128 * 129 + 2 * 128 * 20) * (int)sizeof(float);
    const int sm2 = 2048 * 17 * (int)sizeof(float);                            // 139,264 B
    const int sm3 = 128 * 4 + (128 * 24 + 128 * 72 + 64 * 24 + 64 * 72) * 2;   // 37,376 B
    const int sm4 = 128 * 4 + (128 * 72 + 2 * 64 * 72) * 2;                    // 37,376 B
    cudaFuncSetAttribute(k_poly,  cudaFuncAttributeMaxDynamicSharedMemorySize, sm1);
    cudaFuncSetAttribute(k_mlpbn, cudaFuncAttributeMaxDynamicSharedMemorySize, sm2);
    cudaFuncSetAttribute(k_gin1,  cudaFuncAttributeMaxDynamicSharedMemorySize, sm3);
    cudaFuncSetAttribute(k_gin2,  cudaFuncAttributeMaxDynamicSharedMemorySize, sm4);

    k_poly<<<cB, 512, sm1>>>(lap, W0);
    k_zero<<<(NSUM + 255) / 256, 256>>>();
    k_hist<<<256, 256>>>(ei);
    k_mlpbn<<<cB, 256, sm2>>>(mlpW, mlpb, bng, bnb);
    k_scan<<<1, 512>>>();
    k_scatter<<<256, 256>>>(ei);
    k_gin1<<<NSUM / 8, 256, sm3>>>(eps1, W1a, b1a, W1b, b1b);
    k_gin2<<<NSUM / 8, 512, sm4>>>(eps2, W2a, b2a, W2b, b2b, out);
}